// round 11
// baseline (speedup 1.0000x reference)
#include <cuda_runtime.h>
#include <cuda_bf16.h>

#define SPD   48
#define VOX   (48*48*48)      /* 110592 */
#define CH    96
#define CH4   384
#define LATD  8
#define STY   128
#define NB    2

/* k_gemm12 dynamic smem layout (bytes) */
#define AS_OFF   0            /* 128 x 104 bf16 = 26624 */
#define W1B0     26624        /* 64 x 104 bf16 = 13312 */
#define W1B1     39936
#define W2B0     53248        /* 96 x 72 bf16 = 13824 */
#define W2B1     67072
#define HS_OFF   53248        /* stage-A alias: 96 x 136 bf16 = 26112 (over W2B0+W2B1) */
#define FG_SMEM  80896

/* ---------------- scratch (device globals; no allocation) ---------------- */
__device__ float g_wdw[NB * CH * 343];
__device__ float g_bdw[NB * CH];
__device__ __nv_bfloat16 g_W1h[NB * CH4 * CH];               /* pw1 weights bf16 [o][c]  */
__device__ float g_b1[NB * CH4];
__device__ __nv_bfloat16 g_W2h[NB * CH * CH4];               /* pw2 weights bf16 [o][c4] */
__device__ float g_b2[NB * CH];
__device__ __nv_bfloat16 g_hb[(size_t)NB * CH * VOX];        /* dwconv out, [b][c][v] bf16 */

/* ---------------- helpers ---------------- */
__device__ __forceinline__ unsigned long long pack2(float lo, float hi) {
    unsigned long long r;
    asm("mov.b64 %0, {%1, %2};" : "=l"(r) : "f"(lo), "f"(hi));
    return r;
}
__device__ __forceinline__ void unpack2(unsigned long long v, float& lo, float& hi) {
    asm("mov.b64 {%0, %1}, %2;" : "=f"(lo), "=f"(hi) : "l"(v));
}
__device__ __forceinline__ void fma2(unsigned long long& d, unsigned long long a, unsigned long long b) {
    asm("fma.rn.f32x2 %0, %1, %2, %0;" : "+l"(d) : "l"(a), "l"(b));
}
__device__ __forceinline__ float gelu_fast(float x) {
    float u = 0.7978845608f * x * (1.0f + 0.044715f * x * x);
    float t;
    asm("tanh.approx.f32 %0, %1;" : "=f"(t) : "f"(u));
    return 0.5f * x * (1.0f + t);
}
__device__ __forceinline__ void ldsm_x4(unsigned& r0, unsigned& r1, unsigned& r2, unsigned& r3,
                                        unsigned addr) {
    asm volatile("ldmatrix.sync.aligned.m8n8.x4.shared.b16 {%0,%1,%2,%3}, [%4];"
                 : "=r"(r0), "=r"(r1), "=r"(r2), "=r"(r3) : "r"(addr));
}
__device__ __forceinline__ void mma16816(float* c, const unsigned* a, const unsigned* b) {
    asm volatile("mma.sync.aligned.m16n8k16.row.col.f32.bf16.bf16.f32 "
                 "{%0,%1,%2,%3}, {%4,%5,%6,%7}, {%8,%9}, {%0,%1,%2,%3};"
                 : "+f"(c[0]), "+f"(c[1]), "+f"(c[2]), "+f"(c[3])
                 : "r"(a[0]), "r"(a[1]), "r"(a[2]), "r"(a[3]), "r"(b[0]), "r"(b[1]));
}
__device__ __forceinline__ void cpa16(unsigned dst, const void* src) {
    asm volatile("cp.async.cg.shared.global [%0], [%1], 16;" :: "r"(dst), "l"(src));
}
#define CPA_COMMIT() asm volatile("cp.async.commit_group;" ::: "memory")
#define CPA_WAIT0()  asm volatile("cp.async.wait_group 0;" ::: "memory")

/* ---------------- K0: hyper-weight materialization (unchanged) ---------------- */
__global__ void k_weights(const float* __restrict__ s,
    const float* __restrict__ dw_fc_w,  const float* __restrict__ dw_fc_b,
    const float* __restrict__ dw_bank,  const float* __restrict__ dw_bias_bank,
    const float* __restrict__ pw1_fc_w, const float* __restrict__ pw1_fc_b,
    const float* __restrict__ pw1_bank, const float* __restrict__ pw1_bias_bank,
    const float* __restrict__ pw2_fc_w, const float* __restrict__ pw2_fc_b,
    const float* __restrict__ pw2_bank, const float* __restrict__ pw2_bias_bank)
{
    const int stage = blockIdx.y;
    const int b = blockIdx.z;
    __shared__ float z[LATD];
    const float* fcw = (stage == 0) ? dw_fc_w : (stage == 1) ? pw1_fc_w : pw2_fc_w;
    const float* fcb = (stage == 0) ? dw_fc_b : (stage == 1) ? pw1_fc_b : pw2_fc_b;
    if (threadIdx.x < LATD) {
        float acc = fcb[threadIdx.x];
        for (int j = 0; j < STY; j++) acc += s[b * STY + j] * fcw[threadIdx.x * STY + j];
        z[threadIdx.x] = acc;
    }
    __syncthreads();
    const int idx = blockIdx.x * blockDim.x + threadIdx.x;
    if (stage == 0) {
        const int NW = CH * 343;
        if (idx < NW) {
            float a = 0.f;
            #pragma unroll
            for (int l = 0; l < LATD; l++) a += dw_bank[(size_t)idx * LATD + l] * z[l];
            g_wdw[b * NW + idx] = a;
        } else if (idx < NW + CH) {
            const int c = idx - NW; float a = 0.f;
            #pragma unroll
            for (int l = 0; l < LATD; l++) a += dw_bias_bank[c * LATD + l] * z[l];
            g_bdw[b * CH + c] = a;
        }
    } else if (stage == 1) {
        const int NW = CH4 * CH;
        if (idx < NW) {
            float a = 0.f;
            #pragma unroll
            for (int l = 0; l < LATD; l++) a += pw1_bank[(size_t)idx * LATD + l] * z[l];
            g_W1h[b * NW + idx] = __float2bfloat16(a);
        } else if (idx < NW + CH4) {
            const int o = idx - NW; float a = 0.f;
            #pragma unroll
            for (int l = 0; l < LATD; l++) a += pw1_bias_bank[o * LATD + l] * z[l];
            g_b1[b * CH4 + o] = a;
        }
    } else {
        const int NW = CH * CH4;
        if (idx < NW) {
            float a = 0.f;
            #pragma unroll
            for (int l = 0; l < LATD; l++) a += pw2_bank[(size_t)idx * LATD + l] * z[l];
            g_W2h[b * NW + idx] = __float2bfloat16(a);
        } else if (idx < NW + CH) {
            const int o = idx - NW; float a = 0.f;
            #pragma unroll
            for (int l = 0; l < LATD; l++) a += pw2_bias_bank[o * LATD + l] * z[l];
            g_b2[b * CH + o] = a;
        }
    }
}

/* ---------------- K1: depthwise 7^3 conv, row-sliding f32x2 (unchanged) ---------------- */
__global__ __launch_bounds__(384) void k_dwconv(const float* __restrict__ x)
{
    const int d_t = blockIdx.x / 3, h_t = blockIdx.x % 3;
    const int c = blockIdx.y, b = blockIdx.z;

    extern __shared__ __align__(16) float smx[];        /* 22*22*56 = 108416 B */
    __shared__ __align__(8) float2 wgt2[343];
    __shared__ float sbias;

    const float* xin = x + (size_t)(b * CH + c) * VOX;
    for (int i = threadIdx.x; i < 343; i += 384) {
        const float wv = g_wdw[(b * CH + c) * 343 + i];
        wgt2[i] = make_float2(wv, wv);
    }
    if (threadIdx.x == 0) sbias = g_bdw[b * CH + c];

    const int d0 = d_t * 16 - 3, h0 = h_t * 16 - 3;
    for (int i = threadIdx.x; i < 22 * 22 * 56; i += 384) {
        const int dd = i / 1232;
        const int r  = i - dd * 1232;
        const int hh = r / 56;
        const int ww = r - hh * 56;
        const int gd = d0 + dd, gh = h0 + hh, gw = ww - 3;
        float v = 0.f;
        if ((unsigned)gd < 48u && (unsigned)gh < 48u && (unsigned)gw < 48u)
            v = xin[gd * 2304 + gh * 48 + gw];
        smx[i] = v;
    }
    __syncthreads();

    const int wseg = threadIdx.x % 6;
    const int rr   = threadIdx.x / 6;
    const int hseg = rr & 3;
    const int ld   = rr >> 2;
    const int w0 = wseg * 8, lh = hseg * 4;

    unsigned long long acc2[4][4];
    #pragma unroll
    for (int i = 0; i < 4; i++)
        #pragma unroll
        for (int j = 0; j < 4; j++) acc2[i][j] = 0ull;

    #pragma unroll 1
    for (int kd = 0; kd < 7; kd++) {
        const float* plane = &smx[(ld + kd) * 1232];
        #pragma unroll
        for (int hr = 0; hr < 10; hr++) {
            const float* row = plane + (lh + hr) * 56 + w0;
            float r[16];
            *(float4*)&r[0]  = *(const float4*)&row[0];
            *(float4*)&r[4]  = *(const float4*)&row[4];
            *(float4*)&r[8]  = *(const float4*)&row[8];
            *(float4*)&r[12] = *(const float4*)&row[12];
            unsigned long long Pe[7], Po[6];
            #pragma unroll
            for (int j = 0; j < 7; j++) Pe[j] = pack2(r[2 * j], r[2 * j + 1]);
            #pragma unroll
            for (int j = 0; j < 6; j++) Po[j] = pack2(r[2 * j + 1], r[2 * j + 2]);
            #pragma unroll
            for (int oh = 0; oh < 4; oh++) {
                const int kh = hr - oh;
                if (kh >= 0 && kh < 7) {
                    const unsigned long long* wp =
                        (const unsigned long long*)&wgt2[kd * 49 + kh * 7];
                    #pragma unroll
                    for (int kw = 0; kw < 7; kw++) {
                        const unsigned long long b2 = wp[kw];
                        const int t = kw >> 1;
                        if (kw & 1) {
                            #pragma unroll
                            for (int j = 0; j < 4; j++) fma2(acc2[oh][j], Po[t + j], b2);
                        } else {
                            #pragma unroll
                            for (int j = 0; j < 4; j++) fma2(acc2[oh][j], Pe[t + j], b2);
                        }
                    }
                }
            }
        }
    }

    const float bsv = sbias;
    const int gd = d_t * 16 + ld;
    __nv_bfloat16* obase = g_hb + (size_t)(b * CH + c) * VOX + gd * 2304;
    #pragma unroll
    for (int oh = 0; oh < 4; oh++) {
        const int gh = h_t * 16 + lh + oh;
        float a[8];
        #pragma unroll
        for (int j = 0; j < 4; j++) { unpack2(acc2[oh][j], a[2 * j], a[2 * j + 1]); }
        unsigned uw[4];
        #pragma unroll
        for (int j = 0; j < 4; j++) {
            const __nv_bfloat162 p = __floats2bfloat162_rn(a[2 * j] + bsv, a[2 * j + 1] + bsv);
            uw[j] = *(const unsigned*)&p;
        }
        *(uint4*)(obase + gh * 48 + w0) = make_uint4(uw[0], uw[1], uw[2], uw[3]);
    }
}

/* ---------------- K2: FUSED LN + pw1 + GELU + pw2 + residual (v6) ----------------
   Register-chained back-to-back GEMM: each warp owns 16 voxels and the FULL
   64-ch chunk of gemm1; C-fragments of gemm1 convert in-register to
   A-fragments of gemm2 (adjacent n8 pairs). No Ys smem, one sync per chunk. */
__global__ __launch_bounds__(256, 2) void k_gemm12(const float* __restrict__ x,
                                                   const float* __restrict__ gamma,
                                                   const float* __restrict__ ln_w,
                                                   const float* __restrict__ ln_b,
                                                   float* __restrict__ outg)
{
    const int vb = blockIdx.x * 128;
    const int b  = blockIdx.y;
    const int tid = threadIdx.x;

    extern __shared__ __align__(16) char dsm[];
    __nv_bfloat16* Hs = (__nv_bfloat16*)(dsm + HS_OFF);
    float* Cs = (float*)dsm;                  /* epilogue alias of As + W1 bufs */

    __shared__ float sb1[384];
    __shared__ float sb2[96], sgam[96], snw[96], snb[96];
    __shared__ float ps1[256], psq[256];
    __shared__ float smean[128], srstd[128];

    const __nv_bfloat16* Hg  = g_hb + (size_t)b * CH * VOX;
    const __nv_bfloat16* W1g = g_W1h + b * CH4 * CH;
    const __nv_bfloat16* W2g = g_W2h + b * CH * CH4;
    unsigned sbase;
    asm("{ .reg .u64 t; cvta.to.shared.u64 t, %1; cvt.u32.u64 %0, t; }" : "=r"(sbase) : "l"(dsm));

    auto issue_w1 = [&](int kc, int buf) {
        const unsigned w1d = sbase + (buf ? W1B1 : W1B0);
        #pragma unroll
        for (int t = 0; t < 3; t++) {
            const int idx = tid + t * 256;
            const int r = idx / 12, q = idx % 12;
            cpa16(w1d + (r * 104 + q * 8) * 2, W1g + (kc * 64 + r) * CH + q * 8);
        }
    };
    auto issue_w2 = [&](int kc, int buf) {
        const unsigned w2d = sbase + (buf ? W2B1 : W2B0);
        #pragma unroll
        for (int t = 0; t < 3; t++) {
            const int idx = tid + t * 256;
            const int o = idx >> 3, q = idx & 7;
            cpa16(w2d + (o * 72 + q * 8) * 2, W2g + o * CH4 + kc * 64 + q * 8);
        }
    };

    /* g0: W1 chunk 0 (W1B0 disjoint from Hs) */
    issue_w1(0, 0);
    CPA_COMMIT();

    if (tid < 96) {
        sb2[tid] = g_b2[b * CH + tid];
        sgam[tid] = gamma[tid];
        snw[tid] = ln_w[tid];
        snb[tid] = ln_b[tid];
    }
    for (int i = tid; i < 384; i += 256) sb1[i] = g_b1[b * CH4 + i];

    /* ---- Stage A: load H tile [96 ch][128 vox], LayerNorm -> As[v][c] ---- */
    #pragma unroll
    for (int t = 0; t < 6; t++) {
        const int idx = tid + t * 256;
        const int row = idx >> 4, q = idx & 15;
        *(uint4*)&Hs[row * 136 + q * 8] =
            *(const uint4*)(Hg + (size_t)row * VOX + vb + q * 8);
    }
    __syncthreads();
    {
        const int v = tid & 127, c0 = (tid >> 7) * 48;
        float s1 = 0.f, s2 = 0.f;
        #pragma unroll
        for (int c = 0; c < 48; c++) {
            const float f = __bfloat162float(Hs[(c0 + c) * 136 + v]);
            s1 += f; s2 += f * f;
        }
        ps1[tid] = s1; psq[tid] = s2;
    }
    __syncthreads();
    if (tid < 128) {
        const float s1 = ps1[tid] + ps1[tid + 128];
        const float s2 = psq[tid] + psq[tid + 128];
        const float mean = s1 * (1.f / 96.f);
        const float var  = s2 * (1.f / 96.f) - mean * mean;
        smean[tid] = mean;
        srstd[tid] = rsqrtf(var + 1e-6f);
    }
    __syncthreads();
    {
        __nv_bfloat16* As = (__nv_bfloat16*)(dsm + AS_OFF);
        const int v = tid & 127, c0 = (tid >> 7) * 48;
        const float mean = smean[v], rs = srstd[v];
        #pragma unroll
        for (int c = c0; c < c0 + 48; c += 2) {
            const float f0 = __bfloat162float(Hs[c * 136 + v]);
            const float f1 = __bfloat162float(Hs[(c + 1) * 136 + v]);
            const float a0 = (f0 - mean) * rs * snw[c]     + snb[c];
            const float a1 = (f1 - mean) * rs * snw[c + 1] + snb[c + 1];
            *(__nv_bfloat162*)&As[v * 104 + c] = __floats2bfloat162_rn(a0, a1);
        }
    }
    __syncthreads();   /* Hs dead -> safe to prefetch W2 chunk 0 over it */

    /* g1: W2 chunk 0 */
    issue_w2(0, 0);
    CPA_COMMIT();

    /* ---- mainloop: warp owns rows [m0, m0+16) ---- */
    const int w = tid >> 5, l = tid & 31;
    const int m0 = w * 16;
    const unsigned aBase = sbase + AS_OFF;

    const int arow = l & 15, ahalf = l >> 4;
    const int brow = l & 7, bhalf = (l >> 3) & 1, bsub = l >> 4;
    const int g = l >> 2, tig = l & 3;

    float acc2[12][4];
    #pragma unroll
    for (int j = 0; j < 12; j++)
        #pragma unroll
        for (int q = 0; q < 4; q++) acc2[j][q] = 0.f;

    #pragma unroll 1
    for (int kc = 0; kc < 6; kc++) {
        CPA_WAIT0();
        __syncthreads();            /* weights kc visible; chunk kc-1 readers done */
        if (kc < 5) {
            issue_w1(kc + 1, (kc + 1) & 1);
            issue_w2(kc + 1, (kc + 1) & 1);
            CPA_COMMIT();
        }

        const unsigned w1Base = sbase + ((kc & 1) ? W1B1 : W1B0);
        const unsigned w2Base = sbase + ((kc & 1) ? W2B1 : W2B0);

        /* gemm1: Y(16 x 64) = A(16x96) x W1c(64x96)^T, full chunk per warp */
        float acc1[8][4];
        #pragma unroll
        for (int j = 0; j < 8; j++)
            #pragma unroll
            for (int q = 0; q < 4; q++) acc1[j][q] = 0.f;

        #pragma unroll
        for (int kk = 0; kk < 6; kk++) {
            unsigned a[4];
            ldsm_x4(a[0], a[1], a[2], a[3],
                    aBase + ((m0 + arow) * 104 + kk * 16 + ahalf * 8) * 2);
            unsigned bf[8][2];
            #pragma unroll
            for (int jb = 0; jb < 4; jb++) {
                unsigned t0, t1, t2, t3;
                ldsm_x4(t0, t1, t2, t3,
                        w1Base + ((8 * (2 * jb + bsub) + brow) * 104 + kk * 16 + bhalf * 8) * 2);
                bf[2 * jb][0] = t0; bf[2 * jb][1] = t1;
                bf[2 * jb + 1][0] = t2; bf[2 * jb + 1][1] = t3;
            }
            #pragma unroll
            for (int j = 0; j < 8; j++)
                mma16816(acc1[j], a, bf[j]);
        }

        /* bias + gelu, convert C-frags -> gemm2 A-frags in registers */
        unsigned yk[4][4];
        #pragma unroll
        for (int t = 0; t < 4; t++) {
            #pragma unroll
            for (int p = 0; p < 2; p++) {
                const int j = 2 * t + p;
                const int col = j * 8 + tig * 2;
                const float bs0 = sb1[kc * 64 + col], bs1 = sb1[kc * 64 + col + 1];
                const float v0 = gelu_fast(acc1[j][0] + bs0);
                const float v1 = gelu_fast(acc1[j][1] + bs1);
                const float v2 = gelu_fast(acc1[j][2] + bs0);
                const float v3 = gelu_fast(acc1[j][3] + bs1);
                const __nv_bfloat162 p01 = __floats2bfloat162_rn(v0, v1);
                const __nv_bfloat162 p23 = __floats2bfloat162_rn(v2, v3);
                yk[t][2 * p]     = *(const unsigned*)&p01;
                yk[t][2 * p + 1] = *(const unsigned*)&p23;
            }
        }

        /* gemm2 partial: acc2 += Y(16x64) x W2c(96x64)^T, A from registers */
        #pragma unroll
        for (int t = 0; t < 4; t++) {
            unsigned bf[12][2];
            #pragma unroll
            for (int jb = 0; jb < 6; jb++) {
                unsigned t0, t1, t2, t3;
                ldsm_x4(t0, t1, t2, t3,
                        w2Base + ((8 * (2 * jb + bsub) + brow) * 72 + t * 16 + bhalf * 8) * 2);
                bf[2 * jb][0] = t0; bf[2 * jb][1] = t1;
                bf[2 * jb + 1][0] = t2; bf[2 * jb + 1][1] = t3;
            }
            #pragma unroll
            for (int j = 0; j < 12; j++)
                mma16816(acc2[j], yk[t], bf[j]);
        }
    }
    __syncthreads();   /* all reads done before Cs overwrites As/W1 */

    /* epilogue: bias2 + residual through smem transpose */
    #pragma unroll
    for (int j = 0; j < 12; j++) {
        const int col = j * 8 + tig * 2;
        const int r0 = m0 + g;
        Cs[col * 128 + r0]           = acc2[j][0] + sb2[col];
        Cs[(col + 1) * 128 + r0]     = acc2[j][1] + sb2[col + 1];
        Cs[col * 128 + r0 + 8]       = acc2[j][2] + sb2[col];
        Cs[(col + 1) * 128 + r0 + 8] = acc2[j][3] + sb2[col + 1];
    }
    __syncthreads();

    #pragma unroll
    for (int t = 0; t < 12; t++) {
        const int idx = tid + t * 256;
        const int row = idx >> 5, q = idx & 31;
        const size_t oidx = (size_t)(b * CH + row) * VOX + vb + q * 4;
        const float gm = sgam[row];
        const float4 xv = *(const float4*)(x + oidx);
        const float4 cv = *(const float4*)&Cs[row * 128 + q * 4];
        float4 res;
        res.x = xv.x + gm * cv.x;
        res.y = xv.y + gm * cv.y;
        res.z = xv.z + gm * cv.z;
        res.w = xv.w + gm * cv.w;
        *(float4*)(outg + oidx) = res;
    }
}

/* ---------------- launch ---------------- */
extern "C" void kernel_launch(void* const* d_in, const int* in_sizes, int n_in,
                              void* d_out, int out_size)
{
    const float* x            = (const float*)d_in[0];
    const float* s            = (const float*)d_in[1];
    const float* ln_w         = (const float*)d_in[2];
    const float* ln_b         = (const float*)d_in[3];
    const float* gamma        = (const float*)d_in[4];
    const float* dw_fc_w      = (const float*)d_in[5];
    const float* dw_fc_b      = (const float*)d_in[6];
    const float* dw_bank      = (const float*)d_in[7];
    const float* dw_bias_bank = (const float*)d_in[8];
    const float* pw1_fc_w     = (const float*)d_in[9];
    const float* pw1_fc_b     = (const float*)d_in[10];
    const float* pw1_bank     = (const float*)d_in[11];
    const float* pw1_bias_bank= (const float*)d_in[12];
    const float* pw2_fc_w     = (const float*)d_in[13];
    const float* pw2_fc_b     = (const float*)d_in[14];
    const float* pw2_bank     = (const float*)d_in[15];
    const float* pw2_bias_bank= (const float*)d_in[16];
    float* outp = (float*)d_out;

    const int dwSmem = 22 * 22 * 56 * 4;    /* 108416 B dynamic */
    cudaFuncSetAttribute(k_dwconv, cudaFuncAttributeMaxDynamicSharedMemorySize, dwSmem);
    cudaFuncSetAttribute(k_gemm12, cudaFuncAttributeMaxDynamicSharedMemorySize, FG_SMEM);

    k_weights<<<dim3(146, 3, NB), 256>>>(s,
        dw_fc_w, dw_fc_b, dw_bank, dw_bias_bank,
        pw1_fc_w, pw1_fc_b, pw1_bank, pw1_bias_bank,
        pw2_fc_w, pw2_fc_b, pw2_bank, pw2_bias_bank);

    k_dwconv<<<dim3(9, CH, NB), 384, dwSmem>>>(x);

    k_gemm12<<<dim3(VOX / 128, NB, 1), 256, FG_SMEM>>>(x, gamma, ln_w, ln_b, outp);
}

// round 12
// speedup vs baseline: 1.5672x; 1.5672x over previous
#include <cuda_runtime.h>
#include <cuda_bf16.h>

#define SPD   48
#define VOX   (48*48*48)      /* 110592 */
#define CH    96
#define CH4   384
#define LATD  8
#define STY   128
#define NB    2

/* k_gemm12 dynamic smem layout (bytes) */
#define AS_OFF   0            /* 128 x 104 bf16 = 26624 */
#define W1B0     26624        /* 64 x 104 bf16 = 13312 */
#define W1B1     39936
#define W2B0     53248        /* 96 x 72 bf16 = 13824 */
#define W2B1     67072
#define YS_OFF   80896        /* 128 x 72 bf16 = 18432 */
#define HS_OFF   67072        /* stage-A alias: 96 x 136 bf16 = 26112 (over W2B1+Ys) */
#define FG_SMEM  99328

/* ---------------- scratch (device globals; no allocation) ---------------- */
__device__ float g_wdw[NB * CH * 343];
__device__ float g_bdw[NB * CH];
__device__ __nv_bfloat16 g_W1h[NB * CH4 * CH];               /* pw1 weights bf16 [o][c]  */
__device__ float g_b1[NB * CH4];
__device__ __nv_bfloat16 g_W2h[NB * CH * CH4];               /* pw2 weights bf16 [o][c4] */
__device__ float g_b2[NB * CH];
__device__ __nv_bfloat16 g_hb[(size_t)NB * CH * VOX];        /* dwconv out, [b][c][v] bf16 */

/* ---------------- helpers ---------------- */
__device__ __forceinline__ unsigned long long pack2(float lo, float hi) {
    unsigned long long r;
    asm("mov.b64 %0, {%1, %2};" : "=l"(r) : "f"(lo), "f"(hi));
    return r;
}
__device__ __forceinline__ void unpack2(unsigned long long v, float& lo, float& hi) {
    asm("mov.b64 {%0, %1}, %2;" : "=f"(lo), "=f"(hi) : "l"(v));
}
__device__ __forceinline__ void fma2(unsigned long long& d, unsigned long long a, unsigned long long b) {
    asm("fma.rn.f32x2 %0, %1, %2, %0;" : "+l"(d) : "l"(a), "l"(b));
}
__device__ __forceinline__ float gelu_fast(float x) {
    float u = 0.7978845608f * x * (1.0f + 0.044715f * x * x);
    float t;
    asm("tanh.approx.f32 %0, %1;" : "=f"(t) : "f"(u));
    return 0.5f * x * (1.0f + t);
}
__device__ __forceinline__ void ldsm_x4(unsigned& r0, unsigned& r1, unsigned& r2, unsigned& r3,
                                        unsigned addr) {
    asm volatile("ldmatrix.sync.aligned.m8n8.x4.shared.b16 {%0,%1,%2,%3}, [%4];"
                 : "=r"(r0), "=r"(r1), "=r"(r2), "=r"(r3) : "r"(addr));
}
__device__ __forceinline__ void mma16816(float* c, const unsigned* a, const unsigned* b) {
    asm volatile("mma.sync.aligned.m16n8k16.row.col.f32.bf16.bf16.f32 "
                 "{%0,%1,%2,%3}, {%4,%5,%6,%7}, {%8,%9}, {%0,%1,%2,%3};"
                 : "+f"(c[0]), "+f"(c[1]), "+f"(c[2]), "+f"(c[3])
                 : "r"(a[0]), "r"(a[1]), "r"(a[2]), "r"(a[3]), "r"(b[0]), "r"(b[1]));
}
__device__ __forceinline__ void cpa16(unsigned dst, const void* src) {
    asm volatile("cp.async.cg.shared.global [%0], [%1], 16;" :: "r"(dst), "l"(src));
}
#define CPA_COMMIT() asm volatile("cp.async.commit_group;" ::: "memory")
#define CPA_WAIT0()  asm volatile("cp.async.wait_group 0;" ::: "memory")
#define PAIR_BAR(p)  asm volatile("bar.sync %0, 64;" :: "r"((p) + 1) : "memory")

/* ---------------- K0: hyper-weight materialization (unchanged) ---------------- */
__global__ void k_weights(const float* __restrict__ s,
    const float* __restrict__ dw_fc_w,  const float* __restrict__ dw_fc_b,
    const float* __restrict__ dw_bank,  const float* __restrict__ dw_bias_bank,
    const float* __restrict__ pw1_fc_w, const float* __restrict__ pw1_fc_b,
    const float* __restrict__ pw1_bank, const float* __restrict__ pw1_bias_bank,
    const float* __restrict__ pw2_fc_w, const float* __restrict__ pw2_fc_b,
    const float* __restrict__ pw2_bank, const float* __restrict__ pw2_bias_bank)
{
    const int stage = blockIdx.y;
    const int b = blockIdx.z;
    __shared__ float z[LATD];
    const float* fcw = (stage == 0) ? dw_fc_w : (stage == 1) ? pw1_fc_w : pw2_fc_w;
    const float* fcb = (stage == 0) ? dw_fc_b : (stage == 1) ? pw1_fc_b : pw2_fc_b;
    if (threadIdx.x < LATD) {
        float acc = fcb[threadIdx.x];
        for (int j = 0; j < STY; j++) acc += s[b * STY + j] * fcw[threadIdx.x * STY + j];
        z[threadIdx.x] = acc;
    }
    __syncthreads();
    const int idx = blockIdx.x * blockDim.x + threadIdx.x;
    if (stage == 0) {
        const int NW = CH * 343;
        if (idx < NW) {
            float a = 0.f;
            #pragma unroll
            for (int l = 0; l < LATD; l++) a += dw_bank[(size_t)idx * LATD + l] * z[l];
            g_wdw[b * NW + idx] = a;
        } else if (idx < NW + CH) {
            const int c = idx - NW; float a = 0.f;
            #pragma unroll
            for (int l = 0; l < LATD; l++) a += dw_bias_bank[c * LATD + l] * z[l];
            g_bdw[b * CH + c] = a;
        }
    } else if (stage == 1) {
        const int NW = CH4 * CH;
        if (idx < NW) {
            float a = 0.f;
            #pragma unroll
            for (int l = 0; l < LATD; l++) a += pw1_bank[(size_t)idx * LATD + l] * z[l];
            g_W1h[b * NW + idx] = __float2bfloat16(a);
        } else if (idx < NW + CH4) {
            const int o = idx - NW; float a = 0.f;
            #pragma unroll
            for (int l = 0; l < LATD; l++) a += pw1_bias_bank[o * LATD + l] * z[l];
            g_b1[b * CH4 + o] = a;
        }
    } else {
        const int NW = CH * CH4;
        if (idx < NW) {
            float a = 0.f;
            #pragma unroll
            for (int l = 0; l < LATD; l++) a += pw2_bank[(size_t)idx * LATD + l] * z[l];
            g_W2h[b * NW + idx] = __float2bfloat16(a);
        } else if (idx < NW + CH) {
            const int o = idx - NW; float a = 0.f;
            #pragma unroll
            for (int l = 0; l < LATD; l++) a += pw2_bias_bank[o * LATD + l] * z[l];
            g_b2[b * CH + o] = a;
        }
    }
}

/* ---------------- K1: depthwise 7^3 conv, row-sliding f32x2 (unchanged) ---------------- */
__global__ __launch_bounds__(384) void k_dwconv(const float* __restrict__ x)
{
    const int d_t = blockIdx.x / 3, h_t = blockIdx.x % 3;
    const int c = blockIdx.y, b = blockIdx.z;

    extern __shared__ __align__(16) float smx[];        /* 22*22*56 = 108416 B */
    __shared__ __align__(8) float2 wgt2[343];
    __shared__ float sbias;

    const float* xin = x + (size_t)(b * CH + c) * VOX;
    for (int i = threadIdx.x; i < 343; i += 384) {
        const float wv = g_wdw[(b * CH + c) * 343 + i];
        wgt2[i] = make_float2(wv, wv);
    }
    if (threadIdx.x == 0) sbias = g_bdw[b * CH + c];

    const int d0 = d_t * 16 - 3, h0 = h_t * 16 - 3;
    for (int i = threadIdx.x; i < 22 * 22 * 56; i += 384) {
        const int dd = i / 1232;
        const int r  = i - dd * 1232;
        const int hh = r / 56;
        const int ww = r - hh * 56;
        const int gd = d0 + dd, gh = h0 + hh, gw = ww - 3;
        float v = 0.f;
        if ((unsigned)gd < 48u && (unsigned)gh < 48u && (unsigned)gw < 48u)
            v = xin[gd * 2304 + gh * 48 + gw];
        smx[i] = v;
    }
    __syncthreads();

    const int wseg = threadIdx.x % 6;
    const int rr   = threadIdx.x / 6;
    const int hseg = rr & 3;
    const int ld   = rr >> 2;
    const int w0 = wseg * 8, lh = hseg * 4;

    unsigned long long acc2[4][4];
    #pragma unroll
    for (int i = 0; i < 4; i++)
        #pragma unroll
        for (int j = 0; j < 4; j++) acc2[i][j] = 0ull;

    #pragma unroll 1
    for (int kd = 0; kd < 7; kd++) {
        const float* plane = &smx[(ld + kd) * 1232];
        #pragma unroll
        for (int hr = 0; hr < 10; hr++) {
            const float* row = plane + (lh + hr) * 56 + w0;
            float r[16];
            *(float4*)&r[0]  = *(const float4*)&row[0];
            *(float4*)&r[4]  = *(const float4*)&row[4];
            *(float4*)&r[8]  = *(const float4*)&row[8];
            *(float4*)&r[12] = *(const float4*)&row[12];
            unsigned long long Pe[7], Po[6];
            #pragma unroll
            for (int j = 0; j < 7; j++) Pe[j] = pack2(r[2 * j], r[2 * j + 1]);
            #pragma unroll
            for (int j = 0; j < 6; j++) Po[j] = pack2(r[2 * j + 1], r[2 * j + 2]);
            #pragma unroll
            for (int oh = 0; oh < 4; oh++) {
                const int kh = hr - oh;
                if (kh >= 0 && kh < 7) {
                    const unsigned long long* wp =
                        (const unsigned long long*)&wgt2[kd * 49 + kh * 7];
                    #pragma unroll
                    for (int kw = 0; kw < 7; kw++) {
                        const unsigned long long b2 = wp[kw];
                        const int t = kw >> 1;
                        if (kw & 1) {
                            #pragma unroll
                            for (int j = 0; j < 4; j++) fma2(acc2[oh][j], Po[t + j], b2);
                        } else {
                            #pragma unroll
                            for (int j = 0; j < 4; j++) fma2(acc2[oh][j], Pe[t + j], b2);
                        }
                    }
                }
            }
        }
    }

    const float bsv = sbias;
    const int gd = d_t * 16 + ld;
    __nv_bfloat16* obase = g_hb + (size_t)(b * CH + c) * VOX + gd * 2304;
    #pragma unroll
    for (int oh = 0; oh < 4; oh++) {
        const int gh = h_t * 16 + lh + oh;
        float a[8];
        #pragma unroll
        for (int j = 0; j < 4; j++) { unpack2(acc2[oh][j], a[2 * j], a[2 * j + 1]); }
        unsigned uw[4];
        #pragma unroll
        for (int j = 0; j < 4; j++) {
            const __nv_bfloat162 p = __floats2bfloat162_rn(a[2 * j] + bsv, a[2 * j + 1] + bsv);
            uw[j] = *(const unsigned*)&p;
        }
        *(uint4*)(obase + gh * 48 + w0) = make_uint4(uw[0], uw[1], uw[2], uw[3]);
    }
}

/* ---------------- K2: FUSED LN + pw1 + GELU + pw2 + residual (v5 + pair barriers) ----
   256 threads, 2 blocks/SM. 6 chunks of 64 intermediate channels.
   cp.async double-buffered weight prefetch. The mid-chunk Ys dependency is
   pair-local (warps {2p,2p+1} write/read Ys rows [32p,32p+32)), so the
   block-wide mid sync is replaced by bar.sync (p+1), 64. */
__global__ __launch_bounds__(256, 2) void k_gemm12(const float* __restrict__ x,
                                                   const float* __restrict__ gamma,
                                                   const float* __restrict__ ln_w,
                                                   const float* __restrict__ ln_b,
                                                   float* __restrict__ outg)
{
    const int vb = blockIdx.x * 128;
    const int b  = blockIdx.y;
    const int tid = threadIdx.x;

    extern __shared__ __align__(16) char dsm[];
    __nv_bfloat16* Hs = (__nv_bfloat16*)(dsm + HS_OFF);
    float* Cs = (float*)dsm;                  /* epilogue alias of As + W1 bufs */

    __shared__ float sb1[384];
    __shared__ float sb2[96], sgam[96], snw[96], snb[96];
    __shared__ float ps1[256], psq[256];
    __shared__ float smean[128], srstd[128];

    const __nv_bfloat16* Hg  = g_hb + (size_t)b * CH * VOX;
    const __nv_bfloat16* W1g = g_W1h + b * CH4 * CH;
    const __nv_bfloat16* W2g = g_W2h + b * CH * CH4;
    unsigned sbase;
    asm("{ .reg .u64 t; cvta.to.shared.u64 t, %1; cvt.u32.u64 %0, t; }" : "=r"(sbase) : "l"(dsm));

    /* weight chunk prefetch: W1 rows [kc*64,+64) x96 -> 104-stride; W2 96 rows x 64 k -> 72-stride */
    auto issue_w = [&](int kc, int buf) {
        const unsigned w1d = sbase + (buf ? W1B1 : W1B0);
        const unsigned w2d = sbase + (buf ? W2B1 : W2B0);
        #pragma unroll
        for (int t = 0; t < 6; t++) {
            const int idx = tid + t * 256;
            if (idx < 768) {
                const int r = idx / 12, q = idx % 12;
                cpa16(w1d + (r * 104 + q * 8) * 2, W1g + (kc * 64 + r) * CH + q * 8);
            } else {
                const int i2 = idx - 768;
                const int o = i2 >> 3, q = i2 & 7;
                cpa16(w2d + (o * 72 + q * 8) * 2, W2g + o * CH4 + kc * 64 + q * 8);
            }
        }
        CPA_COMMIT();
    };

    /* prefetch chunk 0 immediately (targets W1B0/W2B0, disjoint from Hs) */
    issue_w(0, 0);

    if (tid < 96) {
        sb2[tid] = g_b2[b * CH + tid];
        sgam[tid] = gamma[tid];
        snw[tid] = ln_w[tid];
        snb[tid] = ln_b[tid];
    }
    for (int i = tid; i < 384; i += 256) sb1[i] = g_b1[b * CH4 + i];

    /* ---- Stage A: load H tile [96 ch][128 vox], LayerNorm -> As[v][c] ---- */
    #pragma unroll
    for (int t = 0; t < 6; t++) {
        const int idx = tid + t * 256;
        const int row = idx >> 4, q = idx & 15;
        *(uint4*)&Hs[row * 136 + q * 8] =
            *(const uint4*)(Hg + (size_t)row * VOX + vb + q * 8);
    }
    __syncthreads();
    {
        const int v = tid & 127, c0 = (tid >> 7) * 48;
        float s1 = 0.f, s2 = 0.f;
        #pragma unroll
        for (int c = 0; c < 48; c++) {
            const float f = __bfloat162float(Hs[(c0 + c) * 136 + v]);
            s1 += f; s2 += f * f;
        }
        ps1[tid] = s1; psq[tid] = s2;
    }
    __syncthreads();
    if (tid < 128) {
        const float s1 = ps1[tid] + ps1[tid + 128];
        const float s2 = psq[tid] + psq[tid + 128];
        const float mean = s1 * (1.f / 96.f);
        const float var  = s2 * (1.f / 96.f) - mean * mean;
        smean[tid] = mean;
        srstd[tid] = rsqrtf(var + 1e-6f);
    }
    __syncthreads();
    {
        __nv_bfloat16* As = (__nv_bfloat16*)(dsm + AS_OFF);
        const int v = tid & 127, c0 = (tid >> 7) * 48;
        const float mean = smean[v], rs = srstd[v];
        #pragma unroll
        for (int c = c0; c < c0 + 48; c += 2) {
            const float f0 = __bfloat162float(Hs[c * 136 + v]);
            const float f1 = __bfloat162float(Hs[(c + 1) * 136 + v]);
            const float a0 = (f0 - mean) * rs * snw[c]     + snb[c];
            const float a1 = (f1 - mean) * rs * snw[c + 1] + snb[c + 1];
            *(__nv_bfloat162*)&As[v * 104 + c] = __floats2bfloat162_rn(a0, a1);
        }
    }

    /* ---- mainloop ---- */
    const int w = tid >> 5, l = tid & 31;
    const int pairid = w >> 1;
    const int m0 = pairid * 32;
    const int n1 = (w & 1) * 32;          /* gemm1 warp N offset */
    const int n2 = (w & 1) * 48;          /* gemm2 warp N offset */
    const unsigned aBase = sbase + AS_OFF;
    const unsigned yBase = sbase + YS_OFF;
    __nv_bfloat16* Ys = (__nv_bfloat16*)(dsm + YS_OFF);

    const int arow = l & 15, ahalf = l >> 4;
    const int brow = l & 7, bhalf = (l >> 3) & 1, bsub = l >> 4;
    const int g = l >> 2, tig = l & 3;

    float acc2[2][6][4];
    #pragma unroll
    for (int i = 0; i < 2; i++)
        #pragma unroll
        for (int j = 0; j < 6; j++)
            #pragma unroll
            for (int q = 0; q < 4; q++) acc2[i][j][q] = 0.f;

    #pragma unroll 1
    for (int kc = 0; kc < 6; kc++) {
        CPA_WAIT0();
        __syncthreads();            /* weights kc visible; chunk kc-1 fully done */
        if (kc < 5) issue_w(kc + 1, (kc + 1) & 1);

        const unsigned w1Base = sbase + ((kc & 1) ? W1B1 : W1B0);
        const unsigned w2Base = sbase + ((kc & 1) ? W2B1 : W2B0);

        /* gemm1: (128 x 64) = A(128x96) x W1c(64x96)^T, warp tile 32x32 */
        float acc1[2][4][4];
        #pragma unroll
        for (int i = 0; i < 2; i++)
            #pragma unroll
            for (int j = 0; j < 4; j++)
                #pragma unroll
                for (int q = 0; q < 4; q++) acc1[i][j][q] = 0.f;

        #pragma unroll
        for (int kk = 0; kk < 6; kk++) {
            unsigned a[2][4];
            #pragma unroll
            for (int i = 0; i < 2; i++) {
                const unsigned addr = aBase +
                    ((m0 + 16 * i + arow) * 104 + kk * 16 + ahalf * 8) * 2;
                ldsm_x4(a[i][0], a[i][1], a[i][2], a[i][3], addr);
            }
            unsigned bf[4][2];
            #pragma unroll
            for (int jb = 0; jb < 2; jb++) {
                const unsigned addr = w1Base +
                    ((n1 + 8 * (2 * jb + bsub) + brow) * 104 + kk * 16 + bhalf * 8) * 2;
                unsigned t0, t1, t2, t3;
                ldsm_x4(t0, t1, t2, t3, addr);
                bf[2 * jb][0] = t0; bf[2 * jb][1] = t1;
                bf[2 * jb + 1][0] = t2; bf[2 * jb + 1][1] = t3;
            }
            #pragma unroll
            for (int i = 0; i < 2; i++)
                #pragma unroll
                for (int j = 0; j < 4; j++)
                    mma16816(acc1[i][j], a[i], bf[j]);
        }

        /* bias + gelu -> Ys bf16 (stride 72) */
        #pragma unroll
        for (int i = 0; i < 2; i++) {
            #pragma unroll
            for (int j = 0; j < 4; j++) {
                const int colc = n1 + 8 * j + tig * 2;
                const float bs0 = sb1[kc * 64 + colc], bs1 = sb1[kc * 64 + colc + 1];
                const float v0 = gelu_fast(acc1[i][j][0] + bs0);
                const float v1 = gelu_fast(acc1[i][j][1] + bs1);
                const float v2 = gelu_fast(acc1[i][j][2] + bs0);
                const float v3 = gelu_fast(acc1[i][j][3] + bs1);
                const int r0 = m0 + 16 * i + g;
                *(__nv_bfloat162*)&Ys[r0 * 72 + colc]       = __floats2bfloat162_rn(v0, v1);
                *(__nv_bfloat162*)&Ys[(r0 + 8) * 72 + colc] = __floats2bfloat162_rn(v2, v3);
            }
        }
        PAIR_BAR(pairid);           /* only the owning pair must rendezvous */

        /* gemm2 partial: acc2 += Ys(128x64) x W2c(96x64)^T, warp tile 32x48 */
        #pragma unroll
        for (int kk = 0; kk < 4; kk++) {
            unsigned a[2][4];
            #pragma unroll
            for (int i = 0; i < 2; i++) {
                const unsigned addr = yBase +
                    ((m0 + 16 * i + arow) * 72 + kk * 16 + ahalf * 8) * 2;
                ldsm_x4(a[i][0], a[i][1], a[i][2], a[i][3], addr);
            }
            unsigned bf[6][2];
            #pragma unroll
            for (int jb = 0; jb < 3; jb++) {
                const unsigned addr = w2Base +
                    ((n2 + 8 * (2 * jb + bsub) + brow) * 72 + kk * 16 + bhalf * 8) * 2;
                unsigned t0, t1, t2, t3;
                ldsm_x4(t0, t1, t2, t3, addr);
                bf[2 * jb][0] = t0; bf[2 * jb][1] = t1;
                bf[2 * jb + 1][0] = t2; bf[2 * jb + 1][1] = t3;
            }
            #pragma unroll
            for (int i = 0; i < 2; i++)
                #pragma unroll
                for (int j = 0; j < 6; j++)
                    mma16816(acc2[i][j], a[i], bf[j]);
        }
    }
    __syncthreads();   /* all gemm2 reads done before Cs overwrites As/W1 */

    /* epilogue: bias2 + residual through smem transpose */
    #pragma unroll
    for (int i = 0; i < 2; i++) {
        #pragma unroll
        for (int j = 0; j < 6; j++) {
            const int col = n2 + 8 * j + tig * 2;
            const int r0 = m0 + 16 * i + g;
            Cs[col * 128 + r0]           = acc2[i][j][0] + sb2[col];
            Cs[(col + 1) * 128 + r0]     = acc2[i][j][1] + sb2[col + 1];
            Cs[col * 128 + r0 + 8]       = acc2[i][j][2] + sb2[col];
            Cs[(col + 1) * 128 + r0 + 8] = acc2[i][j][3] + sb2[col + 1];
        }
    }
    __syncthreads();

    #pragma unroll
    for (int t = 0; t < 12; t++) {
        const int idx = tid + t * 256;
        const int row = idx >> 5, q = idx & 31;
        const size_t oidx = (size_t)(b * CH + row) * VOX + vb + q * 4;
        const float gm = sgam[row];
        const float4 xv = *(const float4*)(x + oidx);
        const float4 cv = *(const float4*)&Cs[row * 128 + q * 4];
        float4 res;
        res.x = xv.x + gm * cv.x;
        res.y = xv.y + gm * cv.y;
        res.z = xv.z + gm * cv.z;
        res.w = xv.w + gm * cv.w;
        *(float4*)(outg + oidx) = res;
    }
}

/* ---------------- launch ---------------- */
extern "C" void kernel_launch(void* const* d_in, const int* in_sizes, int n_in,
                              void* d_out, int out_size)
{
    const float* x            = (const float*)d_in[0];
    const float* s            = (const float*)d_in[1];
    const float* ln_w         = (const float*)d_in[2];
    const float* ln_b         = (const float*)d_in[3];
    const float* gamma        = (const float*)d_in[4];
    const float* dw_fc_w      = (const float*)d_in[5];
    const float* dw_fc_b      = (const float*)d_in[6];
    const float* dw_bank      = (const float*)d_in[7];
    const float* dw_bias_bank = (const float*)d_in[8];
    const float* pw1_fc_w     = (const float*)d_in[9];
    const float* pw1_fc_b     = (const float*)d_in[10];
    const float* pw1_bank     = (const float*)d_in[11];
    const float* pw1_bias_bank= (const float*)d_in[12];
    const float* pw2_fc_w     = (const float*)d_in[13];
    const float* pw2_fc_b     = (const float*)d_in[14];
    const float* pw2_bank     = (const float*)d_in[15];
    const float* pw2_bias_bank= (const float*)d_in[16];
    float* outp = (float*)d_out;

    const int dwSmem = 22 * 22 * 56 * 4;    /* 108416 B dynamic */
    cudaFuncSetAttribute(k_dwconv, cudaFuncAttributeMaxDynamicSharedMemorySize, dwSmem);
    cudaFuncSetAttribute(k_gemm12, cudaFuncAttributeMaxDynamicSharedMemorySize, FG_SMEM);

    k_weights<<<dim3(146, 3, NB), 256>>>(s,
        dw_fc_w, dw_fc_b, dw_bank, dw_bias_bank,
        pw1_fc_w, pw1_fc_b, pw1_bank, pw1_bias_bank,
        pw2_fc_w, pw2_fc_b, pw2_bank, pw2_bias_bank);

    k_dwconv<<<dim3(9, CH, NB), 384, dwSmem>>>(x);

    k_gemm12<<<dim3(VOX / 128, NB, 1), 256, FG_SMEM>>>(x, gamma, ln_w, ln_b, outp);
}